// round 9
// baseline (speedup 1.0000x reference)
#include <cuda_runtime.h>
#include <cuda_bf16.h>
#include <math.h>
#include <limits.h>

#define NMAX 200000
#define DM   128
#define VOXQ 8
#define SW   132      // bf16 row stride (in elements) for the staged W tile

// ---------------- device globals (scratch; no allocations allowed) ----------
__device__ int g_min3[3];
__device__ int g_max3[3];
__device__ int g_count;
__device__ float g_wnmax;

struct MSParams {
    int   minc[3];
    float rcf[3];
    float rv0f, rv1f;
};
__device__ MSParams g_p;

__device__ int g_active[(size_t)NMAX];        // candidate row list

// ---------------- helpers ----------------------------------------------------
__device__ __forceinline__ unsigned pack_bf2(float2 v) {
    __nv_bfloat162 h = __floats2bfloat162_rn(v.x, v.y);   // .x = low = first col
    return *(unsigned*)&h;
}

__device__ __forceinline__ void mma_bf16(float* c,
    unsigned a0, unsigned a1, unsigned a2, unsigned a3,
    unsigned b0, unsigned b1)
{
    asm volatile(
        "mma.sync.aligned.m16n8k16.row.col.f32.bf16.bf16.f32 "
        "{%0,%1,%2,%3}, {%4,%5,%6,%7}, {%8,%9}, {%0,%1,%2,%3};"
        : "+f"(c[0]), "+f"(c[1]), "+f"(c[2]), "+f"(c[3])
        : "r"(a0), "r"(a1), "r"(a2), "r"(a3), "r"(b0), "r"(b1));
}

// ---------------- tiny setup kernels ----------------------------------------
__global__ void k_init() {
    if (threadIdx.x < 3) {
        g_min3[threadIdx.x] = INT_MAX;
        g_max3[threadIdx.x] = INT_MIN;
    }
    if (threadIdx.x == 0) g_count = 0;
}

__global__ void k_minmax(const int* __restrict__ coords, int n) {
    int lmin0 = INT_MAX, lmin1 = INT_MAX, lmin2 = INT_MAX;
    int lmax0 = INT_MIN, lmax1 = INT_MIN, lmax2 = INT_MIN;
    for (int i = blockIdx.x * blockDim.x + threadIdx.x; i < n; i += gridDim.x * blockDim.x) {
        int c0 = coords[3*i + 0], c1 = coords[3*i + 1], c2 = coords[3*i + 2];
        lmin0 = min(lmin0, c0); lmax0 = max(lmax0, c0);
        lmin1 = min(lmin1, c1); lmax1 = max(lmax1, c1);
        lmin2 = min(lmin2, c2); lmax2 = max(lmax2, c2);
    }
    #pragma unroll
    for (int o = 16; o > 0; o >>= 1) {
        lmin0 = min(lmin0, __shfl_xor_sync(0xffffffffu, lmin0, o));
        lmin1 = min(lmin1, __shfl_xor_sync(0xffffffffu, lmin1, o));
        lmin2 = min(lmin2, __shfl_xor_sync(0xffffffffu, lmin2, o));
        lmax0 = max(lmax0, __shfl_xor_sync(0xffffffffu, lmax0, o));
        lmax1 = max(lmax1, __shfl_xor_sync(0xffffffffu, lmax1, o));
        lmax2 = max(lmax2, __shfl_xor_sync(0xffffffffu, lmax2, o));
    }
    if ((threadIdx.x & 31) == 0) {
        atomicMin(&g_min3[0], lmin0); atomicMin(&g_min3[1], lmin1); atomicMin(&g_min3[2], lmin2);
        atomicMax(&g_max3[0], lmax0); atomicMax(&g_max3[1], lmax1); atomicMax(&g_max3[2], lmax2);
    }
}

__global__ void k_params(int n) {
    if (threadIdx.x == 0 && blockIdx.x == 0) {
        int r0 = g_max3[0] - g_min3[0];
        int r1 = g_max3[1] - g_min3[1];
        int r2 = g_max3[2] - g_min3[2];
        g_p.minc[0] = g_min3[0]; g_p.minc[1] = g_min3[1]; g_p.minc[2] = g_min3[2];
        g_p.rcf[0] = (float)r0; g_p.rcf[1] = (float)r1; g_p.rcf[2] = (float)r2;
        g_p.rv0f = (float)(r0 / VOXQ + 1);
        g_p.rv1f = (float)(r1 / VOXQ + 1);
    }
}

// max column 2-norm of W_off (for the rigorous screen margin)
__global__ void k_wnorm(const float* __restrict__ W_off) {
    __shared__ float red[96];
    int c = threadIdx.x;          // 96 threads
    float s = 0.f;
    for (int k = 0; k < DM; k++) {
        float v = W_off[k * 96 + c];
        s += v * v;
    }
    red[c] = sqrtf(s);
    __syncthreads();
    if (c == 0) {
        float m = 0.f;
        for (int i = 0; i < 96; i++) m = fmaxf(m, red[i]);
        g_wnmax = m * 1.02f;
    }
}

// ---------------- screen: bf16 HMMA off-logits + conservative window test ----
// 64 rows/block, 128 threads (4 warps, 16 rows each), 96 off cols.
// Also fills out[row] = b_out for every row (candidates overwritten later).
__global__ __launch_bounds__(128)
void k_screen(const float* __restrict__ query, const float* __restrict__ W_off,
              const float* __restrict__ b_off, const float* __restrict__ b_out,
              float* __restrict__ out, int* __restrict__ act_list, int n)
{
    __shared__ __nv_bfloat16 Wcs[96 * SW];    // Wcs[c][k] (c-major)
    __shared__ unsigned rowmask[64 * 3];      // 96-bit per-row in-window mask
    __shared__ float sboff[96];

    int tid  = threadIdx.x;
    int warp = tid >> 5, lane = tid & 31;
    int gid  = lane >> 2, tig = lane & 3;
    int rowbase = blockIdx.x * 64;

    // stage W_off -> bf16, c-major; biases; clear masks
    for (int idx = tid; idx < 96 * DM; idx += 128) {
        int k = idx / 96, c = idx - k * 96;   // coalesced global read
        Wcs[c * SW + k] = __float2bfloat16(W_off[idx]);
    }
    if (tid < 96)  sboff[tid] = b_off[tid];
    if (tid < 192) rowmask[tid] = 0u;
    __syncthreads();

    float rc[3] = { g_p.rcf[0], g_p.rcf[1], g_p.rcf[2] };
    // margin coefficient: err_t <= (2^-8 * 1.3) * ||q|| * wnmax * rcf[d] * 0.5
    float Kc = g_wnmax * (1.3f * 0.5f / 256.0f);

    int r0 = rowbase + warp * 16 + gid;
    int r1 = r0 + 8;
    bool v0 = r0 < n, v1 = r1 < n;
    const float* q0 = query + (size_t)r0 * DM;
    const float* q1 = query + (size_t)r1 * DM;

    float acc[12][4];
    #pragma unroll
    for (int j = 0; j < 12; j++)
        #pragma unroll
        for (int i = 0; i < 4; i++) acc[j][i] = 0.f;

    float s0 = 0.f, s1 = 0.f;
    const float2 z2 = make_float2(0.f, 0.f);

    #pragma unroll
    for (int kt = 0; kt < 8; kt++) {
        int k0 = kt * 16 + 2 * tig;
        float2 qa = v0 ? *(const float2*)(q0 + k0)     : z2;
        float2 qc = v0 ? *(const float2*)(q0 + k0 + 8) : z2;
        float2 qb = v1 ? *(const float2*)(q1 + k0)     : z2;
        float2 qd = v1 ? *(const float2*)(q1 + k0 + 8) : z2;
        s0 += qa.x*qa.x + qa.y*qa.y + qc.x*qc.x + qc.y*qc.y;
        s1 += qb.x*qb.x + qb.y*qb.y + qd.x*qd.x + qd.y*qd.y;
        unsigned a0 = pack_bf2(qa), a1 = pack_bf2(qb);
        unsigned a2 = pack_bf2(qc), a3 = pack_bf2(qd);
        #pragma unroll
        for (int j = 0; j < 12; j++) {
            int c = j * 8 + gid;
            unsigned b0 = *(const unsigned*)&Wcs[c * SW + k0];
            unsigned b1 = *(const unsigned*)&Wcs[c * SW + k0 + 8];
            mma_bf16(acc[j], a0, a1, a2, a3, b0, b1);
        }
    }

    // per-row ||q||: sum across the 4 tig lanes (they partition the 128 cols)
    s0 += __shfl_xor_sync(0xffffffffu, s0, 1);
    s0 += __shfl_xor_sync(0xffffffffu, s0, 2);
    s1 += __shfl_xor_sync(0xffffffffu, s1, 1);
    s1 += __shfl_xor_sync(0xffffffffu, s1, 2);
    float qn0 = sqrtf(s0) * 1.02f;
    float qn1 = sqrtf(s1) * 1.02f;

    unsigned m0[3] = {0u,0u,0u}, m1[3] = {0u,0u,0u};
    #pragma unroll
    for (int j = 0; j < 12; j++) {
        int c0 = j * 8 + 2 * tig, c1 = c0 + 1;
        int d0 = c0 % 3, d1 = c1 % 3;
        float sc0 = (d0 == 0) ? rc[0] : ((d0 == 1) ? rc[1] : rc[2]);
        float sc1 = (d1 == 0) ? rc[0] : ((d1 == 1) ? rc[1] : rc[2]);
        float t00 = (acc[j][0] + sboff[c0]) * (sc0 * 0.5f);
        float t01 = (acc[j][1] + sboff[c1]) * (sc1 * 0.5f);
        float t10 = (acc[j][2] + sboff[c0]) * (sc0 * 0.5f);
        float t11 = (acc[j][3] + sboff[c1]) * (sc1 * 0.5f);
        float e00 = Kc * qn0 * sc0 + 1e-3f, e01 = Kc * qn0 * sc1 + 1e-3f;
        float e10 = Kc * qn1 * sc0 + 1e-3f, e11 = Kc * qn1 * sc1 + 1e-3f;
        unsigned b0 = ((t00 > -1.f - e00 && t00 < 8.f + e00) ? 1u : 0u)
                    | ((t01 > -1.f - e01 && t01 < 8.f + e01) ? 2u : 0u);
        unsigned b1 = ((t10 > -1.f - e10 && t10 < 8.f + e10) ? 1u : 0u)
                    | ((t11 > -1.f - e11 && t11 < 8.f + e11) ? 2u : 0u);
        int word = j >> 2;
        int sh   = ((j & 3) << 3) + 2 * tig;
        m0[word] |= b0 << sh;
        m1[word] |= b1 << sh;
    }
    int lr0 = warp * 16 + gid, lr1 = lr0 + 8;
    #pragma unroll
    for (int w = 0; w < 3; w++) {
        if (m0[w]) atomicOr(&rowmask[lr0 * 3 + w], m0[w]);
        if (m1[w]) atomicOr(&rowmask[lr1 * 3 + w], m1[w]);
    }
    __syncthreads();

    // per-row candidate test: exists p with bits 3p,3p+1,3p+2 all set
    if (tid < 64) {
        int row = rowbase + tid;
        if (row < n) {
            unsigned wm[3] = { rowmask[tid*3], rowmask[tid*3+1], rowmask[tid*3+2] };
            if (wm[0] | wm[1] | wm[2]) {
                bool any = false;
                #pragma unroll
                for (int p = 0; p < 32; p++) {
                    int c = 3 * p;
                    unsigned q0b = (wm[(c    ) >> 5] >> ((c    ) & 31)) & 1u;
                    unsigned q1b = (wm[(c + 1) >> 5] >> ((c + 1) & 31)) & 1u;
                    unsigned q2b = (wm[(c + 2) >> 5] >> ((c + 2) & 31)) & 1u;
                    any |= (q0b & q1b & q2b) != 0u;
                }
                if (any) {
                    int slot = atomicAdd(&g_count, 1);
                    act_list[slot] = row;
                }
            }
        }
    }

    // fill out = b_out for all rows of this tile (exact for non-candidates)
    float bv = b_out[tid];
    for (int r = 0; r < 64; r++) {
        int row = rowbase + r;
        if (row < n) out[(size_t)row * DM + tid] = bv;
    }
}

// ---------------- exact recompute of candidate rows (batched, 8 rows/iter) ---
__global__ __launch_bounds__(128)
void k_cand(const float* __restrict__ query, const int* __restrict__ coords,
            const float* __restrict__ value_fea,
            const float* __restrict__ W_off,  const float* __restrict__ b_off,
            const float* __restrict__ W_attn, const float* __restrict__ b_attn,
            const float* __restrict__ W_val,  const float* __restrict__ b_val,
            const float* __restrict__ W_out,  const float* __restrict__ b_out,
            const int* __restrict__ act_list, float* __restrict__ out, int n)
{
    __shared__ float sq[8][DM];
    __shared__ float slog[8][DM];
    __shared__ float sv[8][DM];
    __shared__ float spre[8][DM];
    __shared__ float sw[8][8];
    __shared__ int   srow[8];
    __shared__ int   sgi[8];

    int tid = threadIdx.x;
    int cnt = g_count;
    int nbatch = (cnt + 7) / 8;

    for (int it = blockIdx.x; it < nbatch; it += gridDim.x) {
        // stage 8 candidate q rows
        if (tid < 8) {
            int idx = it * 8 + tid;
            srow[tid] = (idx < cnt) ? act_list[idx] : -1;
        }
        __syncthreads();
        #pragma unroll
        for (int i = 0; i < 8; i++) {
            int row = srow[i];
            sq[i][tid] = (row >= 0) ? query[(size_t)row * DM + tid] : 0.f;
        }
        __syncthreads();

        // exact logits: [off | attn] for 8 rows (col = tid)
        {
            float a[8];
            #pragma unroll
            for (int i = 0; i < 8; i++) a[i] = 0.f;
            int c = tid;
            if (c < 96) {
                for (int k = 0; k < DM; k++) {
                    float wv = W_off[k * 96 + c];
                    #pragma unroll
                    for (int i = 0; i < 8; i++) a[i] = fmaf(sq[i][k], wv, a[i]);
                }
                #pragma unroll
                for (int i = 0; i < 8; i++) slog[i][c] = a[i] + b_off[c];
            } else {
                int ca = c - 96;
                for (int k = 0; k < DM; k++) {
                    float wv = W_attn[k * 32 + ca];
                    #pragma unroll
                    for (int i = 0; i < 8; i++) a[i] = fmaf(sq[i][k], wv, a[i]);
                }
                #pragma unroll
                for (int i = 0; i < 8; i++) slog[i][c] = a[i] + b_attn[ca];
            }
        }
        __syncthreads();

        // mask + softmax -> per-head weights; gather index per row
        if (tid < 64) {
            int r = tid >> 3, h = tid & 7;
            float l[4], e[4];
            #pragma unroll
            for (int p = 0; p < 4; p++) l[p] = slog[r][96 + h*4 + p];
            float mx = fmaxf(fmaxf(l[0], l[1]), fmaxf(l[2], l[3]));
            float s = 0.f;
            #pragma unroll
            for (int p = 0; p < 4; p++) { e[p] = expf(l[p] - mx); s += e[p]; }
            float num = 0.f;
            #pragma unroll
            for (int p = 0; p < 4; p++) {
                int base = (h*4 + p) * 3;
                float t0 = (slog[r][base + 0] * g_p.rcf[0]) * 0.5f;
                float t1 = (slog[r][base + 1] * g_p.rcf[1]) * 0.5f;
                float t2 = (slog[r][base + 2] * g_p.rcf[2]) * 0.5f;
                int a0 = (int)t0, a1 = (int)t1, a2 = (int)t2;  // trunc toward 0
                unsigned u = (unsigned)a0 | (unsigned)a1 | (unsigned)a2;
                if (u < 8u) num += e[p];
            }
            sw[r][h] = num / s;
        }
        if (tid < 8) {
            int row = srow[tid];
            int gi = 0;
            if (row >= 0) {
                int c0 = coords[3*row + 0], c1 = coords[3*row + 1], c2 = coords[3*row + 2];
                float i0 = (float)(c0 - g_p.minc[0]) * 0.125f;
                float i1 = (float)(c1 - g_p.minc[1]) * 0.125f;
                float i2 = (float)(c2 - g_p.minc[2]) * 0.125f;
                float flat = i0 * g_p.rv1f * g_p.rv0f + i1 * g_p.rv0f + i2;
                gi = (int)floorf(flat);
                gi = gi < 0 ? 0 : (gi > n - 1 ? n - 1 : gi);
            }
            sgi[tid] = gi;
        }
        __syncthreads();

        // stage gathered value_fea rows
        #pragma unroll
        for (int i = 0; i < 8; i++)
            sv[i][tid] = value_fea[(size_t)sgi[i] * DM + tid];
        __syncthreads();

        // value GEMV + weight scale
        {
            float a[8];
            #pragma unroll
            for (int i = 0; i < 8; i++) a[i] = 0.f;
            for (int k = 0; k < DM; k++) {
                float wv = W_val[k * DM + tid];
                #pragma unroll
                for (int i = 0; i < 8; i++) a[i] = fmaf(sv[i][k], wv, a[i]);
            }
            float bv = b_val[tid];
            int hh = tid >> 4;
            #pragma unroll
            for (int i = 0; i < 8; i++) spre[i][tid] = (a[i] + bv) * sw[i][hh];
        }
        __syncthreads();

        // out GEMV
        {
            float a[8];
            #pragma unroll
            for (int i = 0; i < 8; i++) a[i] = 0.f;
            for (int k = 0; k < DM; k++) {
                float wv = W_out[k * DM + tid];
                #pragma unroll
                for (int i = 0; i < 8; i++) a[i] = fmaf(spre[i][k], wv, a[i]);
            }
            float bv = b_out[tid];
            #pragma unroll
            for (int i = 0; i < 8; i++) {
                int row = srow[i];
                if (row >= 0) out[(size_t)row * DM + tid] = a[i] + bv;
            }
        }
        __syncthreads();
    }
}

// ---------------- launcher ---------------------------------------------------
extern "C" void kernel_launch(void* const* d_in, const int* in_sizes, int n_in,
                              void* d_out, int out_size)
{
    const float* query     = (const float*)d_in[0];
    const float* value_fea = (const float*)d_in[1];
    const int*   coords    = (const int*)  d_in[2];
    const float* W_off     = (const float*)d_in[3];
    const float* b_off     = (const float*)d_in[4];
    const float* W_attn    = (const float*)d_in[5];
    const float* b_attn    = (const float*)d_in[6];
    const float* W_val     = (const float*)d_in[7];
    const float* b_val     = (const float*)d_in[8];
    const float* W_out     = (const float*)d_in[9];
    const float* b_out     = (const float*)d_in[10];
    float* out = (float*)d_out;

    int n = in_sizes[0] / DM;
    if (n > NMAX) n = NMAX;

    int* gact = nullptr;
    cudaGetSymbolAddress((void**)&gact, g_active);

    k_init  <<<1, 32>>>();
    k_minmax<<<592, 256>>>(coords, n);
    k_params<<<1, 1>>>(n);
    k_wnorm <<<1, 96>>>(W_off);

    // bf16 tensor-core screen + out = b_out fill
    k_screen<<<(n + 63) / 64, 128>>>(query, W_off, b_off, b_out, out, gact, n);

    // exact fp32 recompute of candidate rows
    k_cand<<<296, 128>>>(query, coords, value_fea,
                         W_off, b_off, W_attn, b_attn,
                         W_val, b_val, W_out, b_out,
                         gact, out, n);
}

// round 10
// speedup vs baseline: 5.1195x; 5.1195x over previous
#include <cuda_runtime.h>
#include <math.h>
#include <limits.h>

#define NMAX 200000
#define DM   128
#define VOXQ 8

// packed dual-fp32 FMA (sm_100+): each 32-bit lane is a full rn FMA
#define FMA2(acc, a, w) \
    asm("fma.rn.f32x2 %0, %1, %2, %0;" : "+l"(acc) : "l"(a), "l"(w))
#define BCAST2(dst, fv) \
    asm("mov.b64 %0, {%1, %1};" : "=l"(dst) : "r"(__float_as_uint(fv)))

__device__ __forceinline__ float f2lo(unsigned long long v) {
    return __uint_as_float((unsigned)v);
}
__device__ __forceinline__ float f2hi(unsigned long long v) {
    return __uint_as_float((unsigned)(v >> 32));
}

// ---------------- device globals (scratch; no allocations allowed) ----------
__device__ int g_min3[3];
__device__ int g_max3[3];
__device__ int g_count;

struct MSParams {
    int   minc[3];
    float rcf[3];
    float rv0f, rv1f;
};
__device__ MSParams g_p;

__device__ float g_w8[(size_t)NMAX * 8];      // per-row per-head weight
__device__ int   g_gi[(size_t)NMAX];          // per-row gather index
__device__ int   g_active[(size_t)NMAX];      // compacted active row list

// ---------------- tiny setup kernels ----------------------------------------
__global__ void k_init() {
    if (threadIdx.x < 3) {
        g_min3[threadIdx.x] = INT_MAX;
        g_max3[threadIdx.x] = INT_MIN;
    }
    if (threadIdx.x == 0) g_count = 0;
}

__global__ void k_minmax(const int* __restrict__ coords, int n) {
    int lmin0 = INT_MAX, lmin1 = INT_MAX, lmin2 = INT_MAX;
    int lmax0 = INT_MIN, lmax1 = INT_MIN, lmax2 = INT_MIN;
    for (int i = blockIdx.x * blockDim.x + threadIdx.x; i < n; i += gridDim.x * blockDim.x) {
        int c0 = coords[3*i + 0], c1 = coords[3*i + 1], c2 = coords[3*i + 2];
        lmin0 = min(lmin0, c0); lmax0 = max(lmax0, c0);
        lmin1 = min(lmin1, c1); lmax1 = max(lmax1, c1);
        lmin2 = min(lmin2, c2); lmax2 = max(lmax2, c2);
    }
    #pragma unroll
    for (int o = 16; o > 0; o >>= 1) {
        lmin0 = min(lmin0, __shfl_xor_sync(0xffffffffu, lmin0, o));
        lmin1 = min(lmin1, __shfl_xor_sync(0xffffffffu, lmin1, o));
        lmin2 = min(lmin2, __shfl_xor_sync(0xffffffffu, lmin2, o));
        lmax0 = max(lmax0, __shfl_xor_sync(0xffffffffu, lmax0, o));
        lmax1 = max(lmax1, __shfl_xor_sync(0xffffffffu, lmax1, o));
        lmax2 = max(lmax2, __shfl_xor_sync(0xffffffffu, lmax2, o));
    }
    if ((threadIdx.x & 31) == 0) {
        atomicMin(&g_min3[0], lmin0); atomicMin(&g_min3[1], lmin1); atomicMin(&g_min3[2], lmin2);
        atomicMax(&g_max3[0], lmax0); atomicMax(&g_max3[1], lmax1); atomicMax(&g_max3[2], lmax2);
    }
}

__global__ void k_params(int n) {
    if (threadIdx.x == 0 && blockIdx.x == 0) {
        int r0 = g_max3[0] - g_min3[0];
        int r1 = g_max3[1] - g_min3[1];
        int r2 = g_max3[2] - g_min3[2];
        g_p.minc[0] = g_min3[0]; g_p.minc[1] = g_min3[1]; g_p.minc[2] = g_min3[2];
        g_p.rcf[0] = (float)r0; g_p.rcf[1] = (float)r1; g_p.rcf[2] = (float)r2;
        g_p.rv0f = (float)(r0 / VOXQ + 1);
        g_p.rv1f = (float)(r1 / VOXQ + 1);
    }
}

// ---------------- fused: oa-GEMM (FFMA2) + mask/softmax epi + out=b_out fill -
// Static smem only: As/Ws (16.6 KB) reused as buf[64*132] (33.8 KB) after
// the mainloop -> total well under the 48 KB static limit, 2 CTAs/SM.
__global__ __launch_bounds__(256, 2)
void k_fused(const float* __restrict__ A, const int* __restrict__ coords,
             const float* __restrict__ W1, const float* __restrict__ W2,
             const float* __restrict__ b1, const float* __restrict__ b2,
             const float* __restrict__ b_out,
             float* __restrict__ w8, int* __restrict__ gi_out,
             int* __restrict__ act_list, float* __restrict__ out, int n)
{
    __shared__ __align__(16) char smem_u[64 * 132 * 4];   // union region
    __shared__ __align__(16) float sbout[128];
    __shared__ int sact[64];

    float* As  = (float*)smem_u;          // [16*132] phase 1
    float* Ws  = As + 16 * 132;           // [16*128] phase 1
    float* buf = (float*)smem_u;          // [64*132] phase 2 (reuse)

    const int w1cols = 96, w2cols = 32;
    int m0 = blockIdx.x * 128;
    int tid = threadIdx.x;
    int tx = tid & 15, ty = tid >> 4;

    if (tid < 128) sbout[tid] = b_out[tid];

    unsigned long long acc[8][4];
    #pragma unroll
    for (int i = 0; i < 8; i++)
        #pragma unroll
        for (int j = 0; j < 4; j++) acc[i][j] = 0ull;

    int la_r = tid >> 1;
    int la_c = (tid & 1) * 8;
    int gr = m0 + la_r;
    const float* aRow = (gr < n) ? (A + (size_t)gr * DM + la_c) : (const float*)0;
    int rW = tid >> 5;              // 0..7
    int cW = (tid & 31) << 2;       // 0..124

    float4 pa0 = make_float4(0,0,0,0), pa1 = pa0, pw0, pw1;
    if (aRow) { pa0 = *(const float4*)(aRow); pa1 = *(const float4*)(aRow + 4); }
    pw0 = (cW < w1cols) ? *(const float4*)(W1 + (size_t)rW * w1cols + cW)
                        : *(const float4*)(W2 + (size_t)rW * w2cols + (cW - w1cols));
    pw1 = (cW < w1cols) ? *(const float4*)(W1 + (size_t)(rW+8) * w1cols + cW)
                        : *(const float4*)(W2 + (size_t)(rW+8) * w2cols + (cW - w1cols));

    #pragma unroll 1
    for (int kb = 0; kb < 8; kb++) {
        As[(la_c+0)*132 + la_r] = pa0.x; As[(la_c+1)*132 + la_r] = pa0.y;
        As[(la_c+2)*132 + la_r] = pa0.z; As[(la_c+3)*132 + la_r] = pa0.w;
        As[(la_c+4)*132 + la_r] = pa1.x; As[(la_c+5)*132 + la_r] = pa1.y;
        As[(la_c+6)*132 + la_r] = pa1.z; As[(la_c+7)*132 + la_r] = pa1.w;
        *(float4*)&Ws[rW * 128 + cW]       = pw0;
        *(float4*)&Ws[(rW + 8) * 128 + cW] = pw1;
        __syncthreads();

        if (kb < 7) {
            int ko = (kb + 1) * 16;
            if (aRow) { pa0 = *(const float4*)(aRow + ko); pa1 = *(const float4*)(aRow + ko + 4); }
            pw0 = (cW < w1cols) ? *(const float4*)(W1 + (size_t)(ko+rW) * w1cols + cW)
                                : *(const float4*)(W2 + (size_t)(ko+rW) * w2cols + (cW - w1cols));
            pw1 = (cW < w1cols) ? *(const float4*)(W1 + (size_t)(ko+rW+8) * w1cols + cW)
                                : *(const float4*)(W2 + (size_t)(ko+rW+8) * w2cols + (cW - w1cols));
        }

        #pragma unroll
        for (int k = 0; k < 16; k++) {
            float4 aA = *(const float4*)&As[k*132 + ty*8];
            float4 aB = *(const float4*)&As[k*132 + ty*8 + 4];
            ulonglong2 wA = *(const ulonglong2*)&Ws[k*128 + tx*4];
            ulonglong2 wB = *(const ulonglong2*)&Ws[k*128 + 64 + tx*4];
            unsigned long long wp0 = wA.x, wp1 = wA.y, wp2 = wB.x, wp3 = wB.y;
            float av[8] = {aA.x, aA.y, aA.z, aA.w, aB.x, aB.y, aB.z, aB.w};
            #pragma unroll
            for (int i = 0; i < 8; i++) {
                unsigned long long a2;
                BCAST2(a2, av[i]);
                FMA2(acc[i][0], a2, wp0);
                FMA2(acc[i][1], a2, wp1);
                FMA2(acc[i][2], a2, wp2);
                FMA2(acc[i][3], a2, wp3);
            }
        }
        __syncthreads();
    }

    // bias registers (cols tx*4..+3 from [b1|b2], cols 64+tx*4..+3 likewise)
    float bs0[4], bs1[4];
    #pragma unroll
    for (int j = 0; j < 4; j++) {
        int c0 = tx*4 + j, c1 = 64 + tx*4 + j;
        bs0[j] = (c0 < w1cols) ? b1[c0] : b2[c0 - w1cols];
        bs1[j] = (c1 < w1cols) ? b1[c1] : b2[c1 - w1cols];
    }

    float rc0 = g_p.rcf[0], rc1 = g_p.rcf[1], rc2 = g_p.rcf[2];

    // ======== phase 2: two halves of 64 rows through the smem buffer ========
    #pragma unroll 1
    for (int half = 0; half < 2; half++) {
        if (tid < 64) sact[tid] = 0;
        __syncthreads();   // previous buf/As/Ws reads complete before overwrite

        if ((ty >> 3) == half) {
            int tyl = ty & 7;
            #pragma unroll
            for (int i = 0; i < 8; i++) {
                int rl = tyl * 8 + i;
                buf[rl*132 + tx*4 + 0] = f2lo(acc[i][0]) + bs0[0];
                buf[rl*132 + tx*4 + 1] = f2hi(acc[i][0]) + bs0[1];
                buf[rl*132 + tx*4 + 2] = f2lo(acc[i][1]) + bs0[2];
                buf[rl*132 + tx*4 + 3] = f2hi(acc[i][1]) + bs0[3];
                buf[rl*132 + 64 + tx*4 + 0] = f2lo(acc[i][2]) + bs1[0];
                buf[rl*132 + 64 + tx*4 + 1] = f2hi(acc[i][2]) + bs1[1];
                buf[rl*132 + 64 + tx*4 + 2] = f2lo(acc[i][3]) + bs1[2];
                buf[rl*132 + 64 + tx*4 + 3] = f2hi(acc[i][3]) + bs1[3];
            }
        }
        __syncthreads();

        // epilogue: 4 threads/row, 2 heads each
        {
            int rl   = tid >> 2;       // 0..63
            int quad = tid & 3;
            int row  = m0 + half * 64 + rl;
            if (row < n) {
                const float* rb = &buf[rl * 132];
                #pragma unroll
                for (int hh = 0; hh < 2; hh++) {
                    int h = quad * 2 + hh;
                    float l[4], e[4];
                    #pragma unroll
                    for (int p = 0; p < 4; p++) l[p] = rb[96 + h*4 + p];
                    float mx = fmaxf(fmaxf(l[0], l[1]), fmaxf(l[2], l[3]));
                    float s = 0.f;
                    #pragma unroll
                    for (int p = 0; p < 4; p++) { e[p] = expf(l[p] - mx); s += e[p]; }
                    float num = 0.f;
                    #pragma unroll
                    for (int p = 0; p < 4; p++) {
                        int base = (h*4 + p) * 3;
                        float t0 = (rb[base + 0] * rc0) * 0.5f;
                        float t1 = (rb[base + 1] * rc1) * 0.5f;
                        float t2 = (rb[base + 2] * rc2) * 0.5f;
                        int a0 = (int)t0, a1 = (int)t1, a2 = (int)t2;  // trunc (.astype(int32))
                        unsigned u = (unsigned)a0 | (unsigned)a1 | (unsigned)a2;
                        if (u < 8u) num += e[p];
                    }
                    w8[(size_t)row * 8 + h] = num / s;
                    if (num != 0.f) sact[rl] = 1;   // benign race: all store 1
                }
                if (quad == 0) {
                    int c0 = coords[3*row + 0], c1 = coords[3*row + 1], c2 = coords[3*row + 2];
                    float i0 = (float)(c0 - g_p.minc[0]) * 0.125f;
                    float i1 = (float)(c1 - g_p.minc[1]) * 0.125f;
                    float i2 = (float)(c2 - g_p.minc[2]) * 0.125f;
                    float flat = i0 * g_p.rv1f * g_p.rv0f + i1 * g_p.rv0f + i2;
                    int gi = (int)floorf(flat);
                    gi = gi < 0 ? 0 : (gi > n - 1 ? n - 1 : gi);
                    gi_out[row] = gi;
                }
            }
        }
        __syncthreads();

        if (tid < 64) {
            int row = m0 + half * 64 + tid;
            if (row < n && sact[tid]) {
                int slot = atomicAdd(&g_count, 1);
                act_list[slot] = row;
            }
        }

        // fill out = b_out for this half's rows (exact for non-candidates;
        // candidates overwritten by k_active in the same stream)
        for (int idx = tid; idx < 64 * 32; idx += 256) {
            int r  = idx >> 5;
            int c4 = (idx & 31) << 2;
            int orow = m0 + half * 64 + r;
            if (orow < n)
                *(float4*)(out + (size_t)orow * DM + c4) = *(const float4*)&sbout[c4];
        }
    }
}

// ---------------- active rows: out[row] = (w ⊙ (vf[gi]@W_val+b_val)) @ W_out + b_out
__global__ __launch_bounds__(128)
void k_active(const float* __restrict__ value_fea,
              const float* __restrict__ W_val, const float* __restrict__ b_val,
              const float* __restrict__ W_out, const float* __restrict__ b_out,
              const float* __restrict__ w8, const int* __restrict__ gi,
              const int* __restrict__ act_list, float* __restrict__ out)
{
    __shared__ float svf[128];
    __shared__ float spre[128];
    __shared__ float sw[8];

    int tid = threadIdx.x;
    int cnt = g_count;

    for (int idx = blockIdx.x; idx < cnt; idx += gridDim.x) {
        int row = act_list[idx];
        if (tid < 8) sw[tid] = w8[(size_t)row * 8 + tid];
        int g = gi[row];
        svf[tid] = value_fea[(size_t)g * DM + tid];
        __syncthreads();

        // value row = value_fea[g] @ W_val + b_val, scaled by head weight
        float acc = 0.f;
        #pragma unroll 8
        for (int k = 0; k < DM; k++)
            acc = fmaf(svf[k], W_val[k * DM + tid], acc);
        acc += b_val[tid];
        spre[tid] = acc * sw[tid >> 4];
        __syncthreads();

        // out row = pre @ W_out + b_out
        float acc2 = 0.f;
        #pragma unroll 8
        for (int k = 0; k < DM; k++)
            acc2 = fmaf(spre[k], W_out[k * DM + tid], acc2);
        out[(size_t)row * DM + tid] = acc2 + b_out[tid];
        __syncthreads();
    }
}

// ---------------- launcher ---------------------------------------------------
extern "C" void kernel_launch(void* const* d_in, const int* in_sizes, int n_in,
                              void* d_out, int out_size)
{
    const float* query     = (const float*)d_in[0];
    const float* value_fea = (const float*)d_in[1];
    const int*   coords    = (const int*)  d_in[2];
    const float* W_off     = (const float*)d_in[3];
    const float* b_off     = (const float*)d_in[4];
    const float* W_attn    = (const float*)d_in[5];
    const float* b_attn    = (const float*)d_in[6];
    const float* W_val     = (const float*)d_in[7];
    const float* b_val     = (const float*)d_in[8];
    const float* W_out     = (const float*)d_in[9];
    const float* b_out     = (const float*)d_in[10];
    float* out = (float*)d_out;

    int n = in_sizes[0] / DM;
    if (n > NMAX) n = NMAX;

    float *gw = nullptr;
    int *ggi = nullptr, *gact = nullptr;
    cudaGetSymbolAddress((void**)&gw,   g_w8);
    cudaGetSymbolAddress((void**)&ggi,  g_gi);
    cudaGetSymbolAddress((void**)&gact, g_active);

    int nb = (n + 127) / 128;

    k_init  <<<1, 32>>>();
    k_minmax<<<592, 256>>>(coords, n);
    k_params<<<1, 1>>>(n);

    // fused: logits GEMM + mask/softmax + active-list + out=b_out fill
    k_fused<<<nb, 256>>>(query, coords, W_off, W_attn, b_off, b_attn, b_out,
                         gw, ggi, gact, out, n);

    // exact recompute of the few active rows
    k_active<<<1184, 128>>>(value_fea, W_val, b_val, W_out, b_out, gw, ggi, gact, out);
}

// round 11
// speedup vs baseline: 5.7363x; 1.1205x over previous
#include <cuda_runtime.h>
#include <math.h>
#include <limits.h>

#define NMAX 200000
#define DM   128
#define VOXQ 8
#define NC   96        // off-logit columns

// packed dual-fp32 FMA (sm_100+): each 32-bit lane is a full rn FMA
#define FMA2(acc, a, w) \
    asm("fma.rn.f32x2 %0, %1, %2, %0;" : "+l"(acc) : "l"(a), "l"(w))
#define BCAST2(dst, fv) \
    asm("mov.b64 %0, {%1, %1};" : "=l"(dst) : "r"(__float_as_uint(fv)))

__device__ __forceinline__ float f2lo(unsigned long long v) {
    return __uint_as_float((unsigned)v);
}
__device__ __forceinline__ float f2hi(unsigned long long v) {
    return __uint_as_float((unsigned)(v >> 32));
}

// ---------------- device globals (scratch; no allocations allowed) ----------
__device__ int g_min3[3];
__device__ int g_max3[3];
__device__ int g_count;

struct MSParams {
    int   minc[3];
    float rcf[3];
    float rv0f, rv1f;
};
__device__ MSParams g_p;

__device__ int g_active[(size_t)NMAX];        // compacted active row list

// ---------------- tiny setup kernels ----------------------------------------
__global__ void k_init() {
    if (threadIdx.x < 3) {
        g_min3[threadIdx.x] = INT_MAX;
        g_max3[threadIdx.x] = INT_MIN;
    }
    if (threadIdx.x == 0) g_count = 0;
}

__global__ void k_minmax(const int* __restrict__ coords, int n) {
    int lmin0 = INT_MAX, lmin1 = INT_MAX, lmin2 = INT_MAX;
    int lmax0 = INT_MIN, lmax1 = INT_MIN, lmax2 = INT_MIN;
    for (int i = blockIdx.x * blockDim.x + threadIdx.x; i < n; i += gridDim.x * blockDim.x) {
        int c0 = coords[3*i + 0], c1 = coords[3*i + 1], c2 = coords[3*i + 2];
        lmin0 = min(lmin0, c0); lmax0 = max(lmax0, c0);
        lmin1 = min(lmin1, c1); lmax1 = max(lmax1, c1);
        lmin2 = min(lmin2, c2); lmax2 = max(lmax2, c2);
    }
    #pragma unroll
    for (int o = 16; o > 0; o >>= 1) {
        lmin0 = min(lmin0, __shfl_xor_sync(0xffffffffu, lmin0, o));
        lmin1 = min(lmin1, __shfl_xor_sync(0xffffffffu, lmin1, o));
        lmin2 = min(lmin2, __shfl_xor_sync(0xffffffffu, lmin2, o));
        lmax0 = max(lmax0, __shfl_xor_sync(0xffffffffu, lmax0, o));
        lmax1 = max(lmax1, __shfl_xor_sync(0xffffffffu, lmax1, o));
        lmax2 = max(lmax2, __shfl_xor_sync(0xffffffffu, lmax2, o));
    }
    if ((threadIdx.x & 31) == 0) {
        atomicMin(&g_min3[0], lmin0); atomicMin(&g_min3[1], lmin1); atomicMin(&g_min3[2], lmin2);
        atomicMax(&g_max3[0], lmax0); atomicMax(&g_max3[1], lmax1); atomicMax(&g_max3[2], lmax2);
    }
}

__global__ void k_params(int n) {
    if (threadIdx.x == 0 && blockIdx.x == 0) {
        int r0 = g_max3[0] - g_min3[0];
        int r1 = g_max3[1] - g_min3[1];
        int r2 = g_max3[2] - g_min3[2];
        g_p.minc[0] = g_min3[0]; g_p.minc[1] = g_min3[1]; g_p.minc[2] = g_min3[2];
        g_p.rcf[0] = (float)r0; g_p.rcf[1] = (float)r1; g_p.rcf[2] = (float)r2;
        g_p.rv0f = (float)(r0 / VOXQ + 1);
        g_p.rv1f = (float)(r1 / VOXQ + 1);
    }
}

// ---------------- fused: 96-col off-GEMM (FFMA2) + mask + out=b_out fill -----
// 192 threads: GEMM microtile 8 rows x 8 cols, 12 col-groups x 16 row-groups.
// Static smem union: As[16*132]+Ws[16*96] (14.6 KB) reused as buf[64*100] (25.6 KB).
__global__ __launch_bounds__(192, 2)
void k_fused(const float* __restrict__ A, const float* __restrict__ W1,
             const float* __restrict__ b1, const float* __restrict__ b_out,
             int* __restrict__ act_list, float* __restrict__ out, int n)
{
    __shared__ __align__(16) char smem_u[64 * 100 * 4];   // union region
    __shared__ __align__(16) float sbout[128];
    __shared__ int sact[64];

    float* As  = (float*)smem_u;          // [16*132] phase 1
    float* Ws  = As + 16 * 132;           // [16*96]  phase 1
    float* buf = (float*)smem_u;          // [64*100] phase 2 (reuse)

    int m0 = blockIdx.x * 128;
    int tid = threadIdx.x;
    int tx = tid % 12, ty = tid / 12;     // ty 0..15

    if (tid < 128) sbout[tid] = b_out[tid];

    unsigned long long acc[8][4];
    #pragma unroll
    for (int i = 0; i < 8; i++)
        #pragma unroll
        for (int j = 0; j < 4; j++) acc[i][j] = 0ull;

    // A staging: threads 0..127, one row each
    int gr = m0 + tid;
    const float* aRow = (tid < 128 && gr < n) ? (A + (size_t)gr * DM) : (const float*)0;
    // W staging: all 192 threads, 2 float4 slots each (384 slots = 16k x 96c)
    int s1 = tid, s2 = tid + 192;
    int r1 = s1 / 24, c1 = (s1 % 24) * 4;
    int r2 = s2 / 24, c2 = (s2 % 24) * 4;

    float4 pa[4], pw0, pw1;
    #pragma unroll
    for (int j = 0; j < 4; j++) pa[j] = make_float4(0,0,0,0);
    if (aRow) {
        #pragma unroll
        for (int j = 0; j < 4; j++) pa[j] = *(const float4*)(aRow + j*4);
    }
    pw0 = *(const float4*)(W1 + (size_t)r1 * NC + c1);
    pw1 = *(const float4*)(W1 + (size_t)r2 * NC + c2);

    #pragma unroll 1
    for (int kb = 0; kb < 8; kb++) {
        if (tid < 128) {
            #pragma unroll
            for (int j = 0; j < 4; j++) {
                As[(j*4+0)*132 + tid] = pa[j].x;
                As[(j*4+1)*132 + tid] = pa[j].y;
                As[(j*4+2)*132 + tid] = pa[j].z;
                As[(j*4+3)*132 + tid] = pa[j].w;
            }
        }
        *(float4*)&Ws[r1 * NC + c1] = pw0;
        *(float4*)&Ws[r2 * NC + c2] = pw1;
        __syncthreads();

        if (kb < 7) {
            int ko = (kb + 1) * 16;
            if (aRow) {
                #pragma unroll
                for (int j = 0; j < 4; j++) pa[j] = *(const float4*)(aRow + ko + j*4);
            }
            pw0 = *(const float4*)(W1 + (size_t)(ko + r1) * NC + c1);
            pw1 = *(const float4*)(W1 + (size_t)(ko + r2) * NC + c2);
        }

        #pragma unroll
        for (int k = 0; k < 16; k++) {
            float4 aA = *(const float4*)&As[k*132 + ty*8];
            float4 aB = *(const float4*)&As[k*132 + ty*8 + 4];
            ulonglong2 wA = *(const ulonglong2*)&Ws[k*NC + tx*4];
            ulonglong2 wB = *(const ulonglong2*)&Ws[k*NC + 48 + tx*4];
            unsigned long long wp0 = wA.x, wp1 = wA.y, wp2 = wB.x, wp3 = wB.y;
            float av[8] = {aA.x, aA.y, aA.z, aA.w, aB.x, aB.y, aB.z, aB.w};
            #pragma unroll
            for (int i = 0; i < 8; i++) {
                unsigned long long a2;
                BCAST2(a2, av[i]);
                FMA2(acc[i][0], a2, wp0);
                FMA2(acc[i][1], a2, wp1);
                FMA2(acc[i][2], a2, wp2);
                FMA2(acc[i][3], a2, wp3);
            }
        }
        __syncthreads();
    }

    // biases (all 96 cols are b_off)
    float bs0[4], bs1[4];
    #pragma unroll
    for (int j = 0; j < 4; j++) {
        bs0[j] = b1[tx*4 + j];
        bs1[j] = b1[48 + tx*4 + j];
    }

    float rc0 = g_p.rcf[0], rc1 = g_p.rcf[1], rc2 = g_p.rcf[2];

    // ======== phase 2: two halves of 64 rows through the smem buffer ========
    #pragma unroll 1
    for (int half = 0; half < 2; half++) {
        if (tid < 64) sact[tid] = 0;
        __syncthreads();   // prior buf/As/Ws reads complete before overwrite

        if ((ty >> 3) == half) {
            int tyl = ty & 7;
            #pragma unroll
            for (int i = 0; i < 8; i++) {
                int rl = tyl * 8 + i;
                float4 o0, o1;
                o0.x = f2lo(acc[i][0]) + bs0[0]; o0.y = f2hi(acc[i][0]) + bs0[1];
                o0.z = f2lo(acc[i][1]) + bs0[2]; o0.w = f2hi(acc[i][1]) + bs0[3];
                o1.x = f2lo(acc[i][2]) + bs1[0]; o1.y = f2hi(acc[i][2]) + bs1[1];
                o1.z = f2lo(acc[i][3]) + bs1[2]; o1.w = f2hi(acc[i][3]) + bs1[3];
                *(float4*)&buf[rl*100 + tx*4]      = o0;
                *(float4*)&buf[rl*100 + 48 + tx*4] = o1;
            }
        }
        __syncthreads();

        // mask test: 3 threads/row, ~11 points each
        {
            int rl = tid / 3;          // 0..63
            int q  = tid % 3;
            int row = m0 + half * 64 + rl;
            if (row < n) {
                const float* rb = &buf[rl * 100];
                bool any = false;
                for (int p = q; p < 32; p += 3) {
                    int base = 3 * p;
                    float t0 = (rb[base + 0] * rc0) * 0.5f;
                    float t1 = (rb[base + 1] * rc1) * 0.5f;
                    float t2 = (rb[base + 2] * rc2) * 0.5f;
                    int a0 = (int)t0, a1 = (int)t1, a2 = (int)t2;  // trunc (.astype(int32))
                    unsigned u = (unsigned)a0 | (unsigned)a1 | (unsigned)a2;
                    any |= (u < 8u);
                }
                if (any) sact[rl] = 1;   // benign race: all store 1
            }
        }
        __syncthreads();

        if (tid < 64) {
            int row = m0 + half * 64 + tid;
            if (row < n && sact[tid]) {
                int slot = atomicAdd(&g_count, 1);
                act_list[slot] = row;
            }
        }

        // fill out = b_out for this half's rows (exact for inactive rows;
        // active rows overwritten by k_active later in the same stream)
        for (int idx = tid; idx < 64 * 32; idx += 192) {
            int r  = idx >> 5;
            int c4 = (idx & 31) << 2;
            int orow = m0 + half * 64 + r;
            if (orow < n)
                *(float4*)(out + (size_t)orow * DM + c4) = *(const float4*)&sbout[c4];
        }
    }
}

// ---------------- active rows: full exact recompute per row ------------------
__global__ __launch_bounds__(128)
void k_active(const float* __restrict__ query, const int* __restrict__ coords,
              const float* __restrict__ value_fea,
              const float* __restrict__ W_off,  const float* __restrict__ b_off,
              const float* __restrict__ W_attn, const float* __restrict__ b_attn,
              const float* __restrict__ W_val,  const float* __restrict__ b_val,
              const float* __restrict__ W_out,  const float* __restrict__ b_out,
              const int* __restrict__ act_list, float* __restrict__ out, int n)
{
    __shared__ float sq[DM];
    __shared__ float slog[DM];
    __shared__ float sv[DM];
    __shared__ float spre[DM];
    __shared__ float sw[8];
    __shared__ int   sgi1;

    int tid = threadIdx.x;
    int cnt = g_count;

    for (int idx = blockIdx.x; idx < cnt; idx += gridDim.x) {
        int row = act_list[idx];
        sq[tid] = query[(size_t)row * DM + tid];
        __syncthreads();

        // exact logits [off | attn]
        {
            float a = 0.f;
            if (tid < 96) {
                #pragma unroll 8
                for (int k = 0; k < DM; k++)
                    a = fmaf(sq[k], W_off[k * 96 + tid], a);
                a += b_off[tid];
            } else {
                int c = tid - 96;
                #pragma unroll 8
                for (int k = 0; k < DM; k++)
                    a = fmaf(sq[k], W_attn[k * 32 + c], a);
                a += b_attn[c];
            }
            slog[tid] = a;
        }
        __syncthreads();

        // mask + softmax per head; gather index
        if (tid < 8) {
            int h = tid;
            float l[4], e[4];
            #pragma unroll
            for (int p = 0; p < 4; p++) l[p] = slog[96 + h*4 + p];
            float mx = fmaxf(fmaxf(l[0], l[1]), fmaxf(l[2], l[3]));
            float s = 0.f;
            #pragma unroll
            for (int p = 0; p < 4; p++) { e[p] = expf(l[p] - mx); s += e[p]; }
            float num = 0.f;
            #pragma unroll
            for (int p = 0; p < 4; p++) {
                int base = (h*4 + p) * 3;
                float t0 = (slog[base + 0] * g_p.rcf[0]) * 0.5f;
                float t1 = (slog[base + 1] * g_p.rcf[1]) * 0.5f;
                float t2 = (slog[base + 2] * g_p.rcf[2]) * 0.5f;
                int a0 = (int)t0, a1 = (int)t1, a2 = (int)t2;  // trunc toward 0
                unsigned u = (unsigned)a0 | (unsigned)a1 | (unsigned)a2;
                if (u < 8u) num += e[p];
            }
            sw[h] = num / s;
        }
        if (tid == 0) {
            int c0 = coords[3*row + 0], c1 = coords[3*row + 1], c2 = coords[3*row + 2];
            float i0 = (float)(c0 - g_p.minc[0]) * 0.125f;
            float i1 = (float)(c1 - g_p.minc[1]) * 0.125f;
            float i2 = (float)(c2 - g_p.minc[2]) * 0.125f;
            float flat = i0 * g_p.rv1f * g_p.rv0f + i1 * g_p.rv0f + i2;
            int gi = (int)floorf(flat);
            gi = gi < 0 ? 0 : (gi > n - 1 ? n - 1 : gi);
            sgi1 = gi;
        }
        __syncthreads();

        sv[tid] = value_fea[(size_t)sgi1 * DM + tid];
        __syncthreads();

        // value GEMV + head-weight scale
        {
            float a = 0.f;
            #pragma unroll 8
            for (int k = 0; k < DM; k++)
                a = fmaf(sv[k], W_val[k * DM + tid], a);
            spre[tid] = (a + b_val[tid]) * sw[tid >> 4];
        }
        __syncthreads();

        // out GEMV
        {
            float a = 0.f;
            #pragma unroll 8
            for (int k = 0; k < DM; k++)
                a = fmaf(spre[k], W_out[k * DM + tid], a);
            out[(size_t)row * DM + tid] = a + b_out[tid];
        }
        __syncthreads();
    }
}

// ---------------- launcher ---------------------------------------------------
extern "C" void kernel_launch(void* const* d_in, const int* in_sizes, int n_in,
                              void* d_out, int out_size)
{
    const float* query     = (const float*)d_in[0];
    const float* value_fea = (const float*)d_in[1];
    const int*   coords    = (const int*)  d_in[2];
    const float* W_off     = (const float*)d_in[3];
    const float* b_off     = (const float*)d_in[4];
    const float* W_attn    = (const float*)d_in[5];
    const float* b_attn    = (const float*)d_in[6];
    const float* W_val     = (const float*)d_in[7];
    const float* b_val     = (const float*)d_in[8];
    const float* W_out     = (const float*)d_in[9];
    const float* b_out     = (const float*)d_in[10];
    float* out = (float*)d_out;

    int n = in_sizes[0] / DM;
    if (n > NMAX) n = NMAX;

    int* gact = nullptr;
    cudaGetSymbolAddress((void**)&gact, g_active);

    int nb = (n + 127) / 128;

    k_init  <<<1, 32>>>();
    k_minmax<<<592, 256>>>(coords, n);
    k_params<<<1, 1>>>(n);

    // fused: 96-col off-logits GEMM + mask + active-list + out=b_out fill
    k_fused<<<nb, 192>>>(query, W_off, b_off, b_out, gact, out, n);

    // exact end-to-end recompute of the few active rows
    k_active<<<512, 128>>>(query, coords, value_fea,
                           W_off, b_off, W_attn, b_attn,
                           W_val, b_val, W_out, b_out,
                           gact, out, n);
}

// round 12
// speedup vs baseline: 7.9385x; 1.3839x over previous
#include <cuda_runtime.h>
#include <math.h>
#include <limits.h>

#define NMAX 200000
#define DM   128
#define VOXQ 8
#define NC   96        // off-logit columns

// ---------------- device globals (scratch; no allocations allowed) ----------
__device__ int g_min3[3];
__device__ int g_max3[3];
__device__ int g_count;
__device__ int g_wn_bits;      // max column 2-norm of W_off (float bits, >=0)

struct MSParams {
    int   minc[3];
    float rcf[3];
    float rv0f, rv1f;
    float wnml;                // ||w||max * 1.02 * 1.1 / 1024
};
__device__ MSParams g_p;

__device__ int g_active[(size_t)NMAX];        // candidate row list

// ---------------- helpers ----------------------------------------------------
__device__ __forceinline__ float cvt_tf32(float x) {
    unsigned o;
    asm("cvt.rna.tf32.f32 %0, %1;" : "=r"(o) : "f"(x));
    return __uint_as_float(o);
}

__device__ __forceinline__ void mma_tf32(float* c,
    unsigned a0, unsigned a1, unsigned a2, unsigned a3,
    unsigned b0, unsigned b1)
{
    asm volatile(
        "mma.sync.aligned.m16n8k8.row.col.f32.tf32.tf32.f32 "
        "{%0,%1,%2,%3}, {%4,%5,%6,%7}, {%8,%9}, {%0,%1,%2,%3};"
        : "+f"(c[0]), "+f"(c[1]), "+f"(c[2]), "+f"(c[3])
        : "r"(a0), "r"(a1), "r"(a2), "r"(a3), "r"(b0), "r"(b1));
}

// ---------------- tiny setup kernels ----------------------------------------
__global__ void k_init() {
    if (threadIdx.x < 3) {
        g_min3[threadIdx.x] = INT_MAX;
        g_max3[threadIdx.x] = INT_MIN;
    }
    if (threadIdx.x == 0) { g_count = 0; g_wn_bits = 0; }
}

__global__ void k_minmax(const int* __restrict__ coords, int n) {
    int lmin0 = INT_MAX, lmin1 = INT_MAX, lmin2 = INT_MAX;
    int lmax0 = INT_MIN, lmax1 = INT_MIN, lmax2 = INT_MIN;
    for (int i = blockIdx.x * blockDim.x + threadIdx.x; i < n; i += gridDim.x * blockDim.x) {
        int c0 = coords[3*i + 0], c1 = coords[3*i + 1], c2 = coords[3*i + 2];
        lmin0 = min(lmin0, c0); lmax0 = max(lmax0, c0);
        lmin1 = min(lmin1, c1); lmax1 = max(lmax1, c1);
        lmin2 = min(lmin2, c2); lmax2 = max(lmax2, c2);
    }
    #pragma unroll
    for (int o = 16; o > 0; o >>= 1) {
        lmin0 = min(lmin0, __shfl_xor_sync(0xffffffffu, lmin0, o));
        lmin1 = min(lmin1, __shfl_xor_sync(0xffffffffu, lmin1, o));
        lmin2 = min(lmin2, __shfl_xor_sync(0xffffffffu, lmin2, o));
        lmax0 = max(lmax0, __shfl_xor_sync(0xffffffffu, lmax0, o));
        lmax1 = max(lmax1, __shfl_xor_sync(0xffffffffu, lmax1, o));
        lmax2 = max(lmax2, __shfl_xor_sync(0xffffffffu, lmax2, o));
    }
    if ((threadIdx.x & 31) == 0) {
        atomicMin(&g_min3[0], lmin0); atomicMin(&g_min3[1], lmin1); atomicMin(&g_min3[2], lmin2);
        atomicMax(&g_max3[0], lmax0); atomicMax(&g_max3[1], lmax1); atomicMax(&g_max3[2], lmax2);
    }
}

// max column 2-norm of W_off: one warp per column (96 warps across 12 blocks)
__global__ void k_wnorm(const float* __restrict__ W_off) {
    int warp = blockIdx.x * 8 + (threadIdx.x >> 5);   // 0..95
    int lane = threadIdx.x & 31;
    if (warp >= NC) return;
    float s = 0.f;
    for (int k = lane; k < DM; k += 32) {
        float v = W_off[k * NC + warp];
        s += v * v;
    }
    #pragma unroll
    for (int o = 16; o > 0; o >>= 1) s += __shfl_xor_sync(0xffffffffu, s, o);
    if (lane == 0) atomicMax(&g_wn_bits, __float_as_int(sqrtf(s)));
}

__global__ void k_params(int n) {
    if (threadIdx.x == 0 && blockIdx.x == 0) {
        int r0 = g_max3[0] - g_min3[0];
        int r1 = g_max3[1] - g_min3[1];
        int r2 = g_max3[2] - g_min3[2];
        g_p.minc[0] = g_min3[0]; g_p.minc[1] = g_min3[1]; g_p.minc[2] = g_min3[2];
        g_p.rcf[0] = (float)r0; g_p.rcf[1] = (float)r1; g_p.rcf[2] = (float)r2;
        g_p.rv0f = (float)(r0 / VOXQ + 1);
        g_p.rv1f = (float)(r1 / VOXQ + 1);
        g_p.wnml = __int_as_float(g_wn_bits) * 1.02f * (1.1f / 1024.0f);
    }
}

// ---------------- fused TF32 screen: 128 rows x 96 cols per CTA --------------
// 256 threads = 8 warps; warp w owns rows w*16..w*16+15, all 12 n-tiles.
// mma.m16n8k8 tf32; conversion done at staging. Certified margin -> candidates.
__global__ __launch_bounds__(256, 2)
void k_screen(const float* __restrict__ A, const float* __restrict__ W1,
              const float* __restrict__ b1, const float* __restrict__ b_out,
              int* __restrict__ act_list, float* __restrict__ out, int n)
{
    __shared__ __align__(16) float As[16 * 136];   // tf32 bits, As[k][row]
    __shared__ __align__(16) float Ws[16 * 104];   // tf32 bits, Ws[k][col]
    __shared__ float qn[128];
    __shared__ float sboff[NC];
    __shared__ __align__(16) float sbout[128];
    __shared__ unsigned rowmask[128 * 3];

    int m0 = blockIdx.x * 128;
    int tid = threadIdx.x;
    int warp = tid >> 5, lane = tid & 31;
    int lk = lane & 3, lr = lane >> 2;

    if (tid < 128) sbout[tid] = b_out[tid];
    if (tid < NC)  sboff[tid] = b1[tid];
    rowmask[tid] = 0u; if (tid < 128) rowmask[256 + tid] = 0u;

    float acc[12][4];
    #pragma unroll
    for (int j = 0; j < 12; j++)
        #pragma unroll
        for (int i = 0; i < 4; i++) acc[j][i] = 0.f;

    // staging roles
    int arow = tid >> 1;                 // 0..127
    int ahalf = (tid & 1) * 8;           // k offset within chunk
    int gr = m0 + arow;
    const float* aRow = (gr < n) ? (A + (size_t)gr * DM + ahalf) : (const float*)0;
    int s1 = tid, s2 = tid + 256;        // W float4 slots (384 total)
    int wr1 = s1 / 24, wc1 = (s1 % 24) * 4;
    int wr2 = s2 / 24, wc2 = (s2 % 24) * 4;
    bool hasW2 = (tid < 128);

    float4 pa0 = make_float4(0,0,0,0), pa1 = pa0, pw1f, pw2f = pa0;
    if (aRow) { pa0 = *(const float4*)(aRow); pa1 = *(const float4*)(aRow + 4); }
    pw1f = *(const float4*)(W1 + (size_t)wr1 * NC + wc1);
    if (hasW2) pw2f = *(const float4*)(W1 + (size_t)wr2 * NC + wc2);

    float sq = 0.f;

    #pragma unroll 1
    for (int kb = 0; kb < 8; kb++) {
        // ---- stage A (with exact ||q|| accumulation) + W, converted to tf32 ----
        {
            float av[8] = {pa0.x, pa0.y, pa0.z, pa0.w, pa1.x, pa1.y, pa1.z, pa1.w};
            #pragma unroll
            for (int j = 0; j < 8; j++) {
                sq += av[j] * av[j];
                As[(ahalf + j) * 136 + arow] = cvt_tf32(av[j]);
            }
            Ws[wr1 * 104 + wc1 + 0] = cvt_tf32(pw1f.x);
            Ws[wr1 * 104 + wc1 + 1] = cvt_tf32(pw1f.y);
            Ws[wr1 * 104 + wc1 + 2] = cvt_tf32(pw1f.z);
            Ws[wr1 * 104 + wc1 + 3] = cvt_tf32(pw1f.w);
            if (hasW2) {
                Ws[wr2 * 104 + wc2 + 0] = cvt_tf32(pw2f.x);
                Ws[wr2 * 104 + wc2 + 1] = cvt_tf32(pw2f.y);
                Ws[wr2 * 104 + wc2 + 2] = cvt_tf32(pw2f.z);
                Ws[wr2 * 104 + wc2 + 3] = cvt_tf32(pw2f.w);
            }
        }
        __syncthreads();

        if (kb < 7) {
            int ko = (kb + 1) * 16;
            if (aRow) { pa0 = *(const float4*)(aRow + ko); pa1 = *(const float4*)(aRow + ko + 4); }
            pw1f = *(const float4*)(W1 + (size_t)(ko + wr1) * NC + wc1);
            if (hasW2) pw2f = *(const float4*)(W1 + (size_t)(ko + wr2) * NC + wc2);
        }

        // ---- mma mainloop: 2 k8-steps x 12 n-tiles ----
        int rowbase = warp * 16;
        #pragma unroll
        for (int ks = 0; ks < 2; ks++) {
            int k8 = ks * 8;
            unsigned a0 = __float_as_uint(As[(k8 + lk    ) * 136 + rowbase + lr]);
            unsigned a1 = __float_as_uint(As[(k8 + lk    ) * 136 + rowbase + lr + 8]);
            unsigned a2 = __float_as_uint(As[(k8 + lk + 4) * 136 + rowbase + lr]);
            unsigned a3 = __float_as_uint(As[(k8 + lk + 4) * 136 + rowbase + lr + 8]);
            #pragma unroll
            for (int j = 0; j < 12; j++) {
                unsigned b0 = __float_as_uint(Ws[(k8 + lk    ) * 104 + j*8 + lr]);
                unsigned b1v = __float_as_uint(Ws[(k8 + lk + 4) * 104 + j*8 + lr]);
                mma_tf32(acc[j], a0, a1, a2, a3, b0, b1v);
            }
        }
        __syncthreads();
    }

    // exact per-row ||q||: thread t and t^1 hold the two halves of row t>>1
    sq += __shfl_xor_sync(0xffffffffu, sq, 1);
    if ((tid & 1) == 0) qn[arow] = sqrtf(sq) * 1.02f;
    __syncthreads();

    // ---- epilogue: conservative window test per (row, col) ----
    float rc[3] = { g_p.rcf[0], g_p.rcf[1], g_p.rcf[2] };
    float wnml = g_p.wnml;
    int r0l = warp * 16 + lr, r1l = r0l + 8;
    float ml0 = qn[r0l] * wnml;
    float ml1 = qn[r1l] * wnml;
    unsigned msk0[3] = {0u,0u,0u}, msk1[3] = {0u,0u,0u};

    #pragma unroll
    for (int j = 0; j < 12; j++) {
        int cA = j*8 + 2*lk, cB = cA + 1;
        int dA = cA % 3, dB = cB % 3;
        float sdA = 0.5f * rc[dA], sdB = 0.5f * rc[dB];
        float bA = sboff[cA], bB = sboff[cB];

        float tA0 = (acc[j][0] + bA) * sdA;
        float tB0 = (acc[j][1] + bB) * sdB;
        float tA1 = (acc[j][2] + bA) * sdA;
        float tB1 = (acc[j][3] + bB) * sdB;
        float mA0 = ml0 * sdA + 1e-3f, mB0 = ml0 * sdB + 1e-3f;
        float mA1 = ml1 * sdA + 1e-3f, mB1 = ml1 * sdB + 1e-3f;

        if (tA0 > -1.f - mA0 && tA0 < 8.f + mA0) msk0[cA >> 5] |= 1u << (cA & 31);
        if (tB0 > -1.f - mB0 && tB0 < 8.f + mB0) msk0[cB >> 5] |= 1u << (cB & 31);
        if (tA1 > -1.f - mA1 && tA1 < 8.f + mA1) msk1[cA >> 5] |= 1u << (cA & 31);
        if (tB1 > -1.f - mB1 && tB1 < 8.f + mB1) msk1[cB >> 5] |= 1u << (cB & 31);
    }
    #pragma unroll
    for (int w = 0; w < 3; w++) {
        if (msk0[w]) atomicOr(&rowmask[r0l * 3 + w], msk0[w]);
        if (msk1[w]) atomicOr(&rowmask[r1l * 3 + w], msk1[w]);
    }
    __syncthreads();

    // candidate rows: exists p with bits 3p, 3p+1, 3p+2 all set
    if (tid < 128) {
        int row = m0 + tid;
        if (row < n) {
            unsigned w0 = rowmask[tid*3], w1 = rowmask[tid*3+1], w2 = rowmask[tid*3+2];
            if (w0 | w1 | w2) {
                bool any = false;
                #pragma unroll
                for (int p = 0; p < 32; p++) {
                    int c = 3 * p;
                    unsigned q0b = ((c < 32 ? w0 : (c < 64 ? w1 : w2)) >> (c & 31)) & 1u;
                    int c1i = c + 1;
                    unsigned q1b = ((c1i < 32 ? w0 : (c1i < 64 ? w1 : w2)) >> (c1i & 31)) & 1u;
                    int c2i = c + 2;
                    unsigned q2b = ((c2i < 32 ? w0 : (c2i < 64 ? w1 : w2)) >> (c2i & 31)) & 1u;
                    any |= (q0b & q1b & q2b) != 0u;
                }
                if (any) {
                    int slot = atomicAdd(&g_count, 1);
                    act_list[slot] = row;
                }
            }
        }
    }

    // fill out = b_out (exact for non-candidates; candidates overwritten later)
    for (int idx = tid; idx < 128 * 32; idx += 256) {
        int r  = idx >> 5;
        int c4 = (idx & 31) << 2;
        int orow = m0 + r;
        if (orow < n)
            *(float4*)(out + (size_t)orow * DM + c4) = *(const float4*)&sbout[c4];
    }
}

// ---------------- active rows: full exact fp32 recompute per row -------------
__global__ __launch_bounds__(128)
void k_active(const float* __restrict__ query, const int* __restrict__ coords,
              const float* __restrict__ value_fea,
              const float* __restrict__ W_off,  const float* __restrict__ b_off,
              const float* __restrict__ W_attn, const float* __restrict__ b_attn,
              const float* __restrict__ W_val,  const float* __restrict__ b_val,
              const float* __restrict__ W_out,  const float* __restrict__ b_out,
              const int* __restrict__ act_list, float* __restrict__ out, int n)
{
    __shared__ float sq[DM];
    __shared__ float slog[DM];
    __shared__ float sv[DM];
    __shared__ float spre[DM];
    __shared__ float sw[8];
    __shared__ int   sgi1;

    int tid = threadIdx.x;
    int cnt = g_count;

    for (int idx = blockIdx.x; idx < cnt; idx += gridDim.x) {
        int row = act_list[idx];
        sq[tid] = query[(size_t)row * DM + tid];
        __syncthreads();

        // exact logits [off | attn]
        {
            float a = 0.f;
            if (tid < 96) {
                #pragma unroll 8
                for (int k = 0; k < DM; k++)
                    a = fmaf(sq[k], W_off[k * 96 + tid], a);
                a += b_off[tid];
            } else {
                int c = tid - 96;
                #pragma unroll 8
                for (int k = 0; k < DM; k++)
                    a = fmaf(sq[k], W_attn[k * 32 + c], a);
                a += b_attn[c];
            }
            slog[tid] = a;
        }
        __syncthreads();

        // mask + softmax per head; gather index
        if (tid < 8) {
            int h = tid;
            float l[4], e[4];
            #pragma unroll
            for (int p = 0; p < 4; p++) l[p] = slog[96 + h*4 + p];
            float mx = fmaxf(fmaxf(l[0], l[1]), fmaxf(l[2], l[3]));
            float s = 0.f;
            #pragma unroll
            for (int p = 0; p < 4; p++) { e[p] = expf(l[p] - mx); s += e[p]; }
            float num = 0.f;
            #pragma unroll
            for (int p = 0; p < 4; p++) {
                int base = (h*4 + p) * 3;
                float t0 = (slog[base + 0] * g_p.rcf[0]) * 0.5f;
                float t1 = (slog[base + 1] * g_p.rcf[1]) * 0.5f;
                float t2 = (slog[base + 2] * g_p.rcf[2]) * 0.5f;
                int a0 = (int)t0, a1 = (int)t1, a2 = (int)t2;  // trunc toward 0
                unsigned u = (unsigned)a0 | (unsigned)a1 | (unsigned)a2;
                if (u < 8u) num += e[p];
            }
            sw[h] = num / s;
        }
        if (tid == 0) {
            int c0 = coords[3*row + 0], c1 = coords[3*row + 1], c2 = coords[3*row + 2];
            float i0 = (float)(c0 - g_p.minc[0]) * 0.125f;
            float i1 = (float)(c1 - g_p.minc[1]) * 0.125f;
            float i2 = (float)(c2 - g_p.minc[2]) * 0.125f;
            float flat = i0 * g_p.rv1f * g_p.rv0f + i1 * g_p.rv0f + i2;
            int gi = (int)floorf(flat);
            gi = gi < 0 ? 0 : (gi > n - 1 ? n - 1 : gi);
            sgi1 = gi;
        }
        __syncthreads();

        sv[tid] = value_fea[(size_t)sgi1 * DM + tid];
        __syncthreads();

        // value GEMV + head-weight scale
        {
            float a = 0.f;
            #pragma unroll 8
            for (int k = 0; k < DM; k++)
                a = fmaf(sv[k], W_val[k * DM + tid], a);
            spre[tid] = (a + b_val[tid]) * sw[tid >> 4];
        }
        __syncthreads();

        // out GEMV
        {
            float a = 0.f;
            #pragma unroll 8
            for (int k = 0; k < DM; k++)
                a = fmaf(spre[k], W_out[k * DM + tid], a);
            out[(size_t)row * DM + tid] = a + b_out[tid];
        }
        __syncthreads();
    }
}

// ---------------- launcher ---------------------------------------------------
extern "C" void kernel_launch(void* const* d_in, const int* in_sizes, int n_in,
                              void* d_out, int out_size)
{
    const float* query     = (const float*)d_in[0];
    const float* value_fea = (const float*)d_in[1];
    const int*   coords    = (const int*)  d_in[2];
    const float* W_off     = (const float*)d_in[3];
    const float* b_off     = (const float*)d_in[4];
    const float* W_attn    = (const float*)d_in[5];
    const float* b_attn    = (const float*)d_in[6];
    const float* W_val     = (const float*)d_in[7];
    const float* b_val     = (const float*)d_in[8];
    const float* W_out     = (const float*)d_in[9];
    const float* b_out     = (const float*)d_in[10];
    float* out = (float*)d_out;

    int n = in_sizes[0] / DM;
    if (n > NMAX) n = NMAX;

    int* gact = nullptr;
    cudaGetSymbolAddress((void**)&gact, g_active);

    int nb = (n + 127) / 128;

    k_init  <<<1, 32>>>();
    k_minmax<<<592, 256>>>(coords, n);
    k_wnorm <<<12, 256>>>(W_off);
    k_params<<<1, 1>>>(n);

    // TF32 tensor-core screen (certified margin) + out=b_out fill
    k_screen<<<nb, 256>>>(query, W_off, b_off, b_out, gact, out, n);

    // exact end-to-end recompute of candidate rows
    k_active<<<512, 128>>>(query, coords, value_fea,
                           W_off, b_off, W_attn, b_attn,
                           W_val, b_val, W_out, b_out,
                           gact, out, n);
}